// round 17
// baseline (speedup 1.0000x reference)
#include <cuda_runtime.h>
#include <math.h>
#include <stdint.h>

#define GD 160
#define GH 160
#define GW 160
#define GHW (GH * GW)
#define NP 25000
#define RADF 3.0f
#define PATCHN 20

// fold exp(-0.5*e) into exp2(KLOG2*e)
#define KLOG2 (-0.72134752044448170368f)
// keep contributions with w >= exp(-7.6)  <=>  e2 >= -7.6*log2(e)
#define E2T (-10.964482310756122f)
// exp(-7.6): weight-domain threshold for the inner-loop predicate
#define WTH (5.0045141187542147e-4f)

// volume = 160^3 * 2 floats = 2,048,000 float4 exactly
#define ZERO_CTAS 8000
// 4 gaussians per splat CTA
#define GPC 4
#define SPLAT_CTAS (NP / GPC)

struct PParams {
    float cz, cy, cx;
    float q00, a01, a02;     // pre-scaled (log2-domain) quadratic coeffs
    float b11, b22, b12;
    float inv2q;             // 0.5/q00
    float r0, r1;
    float g;                 // exp2(2*q00): constant ratio-of-ratios along z
    int lz, uz, ly, lx;
    int nx, nyx, valid;
    unsigned magic;          // ceil(2^32 / nx) for division-free t/nx
};

__device__ PParams g_params[NP];

__device__ __forceinline__ float ex2f(float x) {
    float y;
    asm("ex2.approx.f32 %0, %1;" : "=f"(y) : "f"(x));
    return y;
}
__device__ __forceinline__ float sqrt_approx(float x) {
    float y;
    asm("sqrt.approx.f32 %0, %1;" : "=f"(y) : "f"(x));
    return y;
}

// Fused: zero the output volume (1 float4 per thread, exact cover) and
// compute per-gaussian params on the first NP global threads.
__global__ __launch_bounds__(256) void zero_precompute_kernel(
    const float* __restrict__ centers,
    const float* __restrict__ log_scales,
    const float* __restrict__ quats,
    const float* __restrict__ rho,
    float4* __restrict__ out4)
{
    const int gtid = blockIdx.x * 256 + threadIdx.x;
    out4[gtid] = make_float4(0.f, 0.f, 0.f, 0.f);

    const int n = gtid;
    if (n >= NP) return;

    PParams p;

    const float cz = centers[n * 3 + 0] * (float)(GD - 1);
    const float cy = centers[n * 3 + 1] * (float)(GH - 1);
    const float cx = centers[n * 3 + 2] * (float)(GW - 1);

    const float s0 = expf(log_scales[n * 3 + 0]);
    const float s1 = expf(log_scales[n * 3 + 1]);
    const float s2 = expf(log_scales[n * 3 + 2]);

    const float r0v = rho[n * 2 + 0];
    const float r1v = rho[n * 2 + 1];

    const float smax = fmaxf(s0, fmaxf(s1, s2));
    const float rad  = smax * RADF;
    const float amp  = sqrtf(r0v * r0v + r1v * r1v);

    int valid = (amp >= 1e-6f && rad >= 1e-3f);

    const int bz = (int)floorf(cz - rad), by = (int)floorf(cy - rad), bx = (int)floorf(cx - rad);
    const int hz = (int)ceilf(cz + rad),  hy = (int)ceilf(cy + rad),  hx = (int)ceilf(cx + rad);
    const int lz = max(bz, 0), ly = max(by, 0), lx = max(bx, 0);
    const int uz = min(min(hz, GD - 1), bz + PATCHN - 1);
    const int uy = min(min(hy, GH - 1), by + PATCHN - 1);
    const int ux = min(min(hx, GW - 1), bx + PATCHN - 1);
    if (lz > uz || ly > uy || lx > ux) valid = 0;

    p.valid = valid;
    if (valid) {
        float qw = quats[n * 4 + 0], qx = quats[n * 4 + 1];
        float qy = quats[n * 4 + 2], qz = quats[n * 4 + 3];
        float nq = fmaxf(sqrtf(qw * qw + qx * qx + qy * qy + qz * qz), 1e-6f);
        float inq = 1.0f / nq;
        qw *= inq; qx *= inq; qy *= inq; qz *= inq;

        const float ww = qw * qw, xx = qx * qx, yy = qy * qy, zz = qz * qz;
        const float wx = qw * qx, wy = qw * qy, wz = qw * qz;
        const float xy = qx * qy, xz = qx * qz, yz = qy * qz;

        const float R00 = ww + xx - yy - zz, R01 = 2.f * (xy - wz), R02 = 2.f * (xz + wy);
        const float R10 = 2.f * (xy + wz),   R11 = ww - xx + yy - zz, R12 = 2.f * (yz - wx);
        const float R20 = 2.f * (xz - wy),   R21 = 2.f * (yz + wx),   R22 = ww - xx - yy + zz;

        const float c0 = fmaxf(s0, 1e-4f), c1 = fmaxf(s1, 1e-4f), c2 = fmaxf(s2, 1e-4f);
        const float i0 = 1.0f / (c0 * c0), i1 = 1.0f / (c1 * c1), i2 = 1.0f / (c2 * c2);

        const float p00 = R00 * R00 * i0 + R01 * R01 * i1 + R02 * R02 * i2;
        const float p11 = R10 * R10 * i0 + R11 * R11 * i1 + R12 * R12 * i2;
        const float p22 = R20 * R20 * i0 + R21 * R21 * i1 + R22 * R22 * i2;
        const float p01 = R00 * R10 * i0 + R01 * R11 * i1 + R02 * R12 * i2;
        const float p02 = R00 * R20 * i0 + R01 * R21 * i1 + R02 * R22 * i2;
        const float p12 = R10 * R20 * i0 + R11 * R21 * i1 + R12 * R22 * i2;

        const float q00 = KLOG2 * p00;
        p.cz = cz; p.cy = cy; p.cx = cx;
        p.q00 = q00;
        p.a01 = 2.0f * KLOG2 * p01;
        p.a02 = 2.0f * KLOG2 * p02;
        p.b11 = KLOG2 * p11;
        p.b22 = KLOG2 * p22;
        p.b12 = 2.0f * KLOG2 * p12;
        p.inv2q = 0.5f / q00;
        p.r0 = r0v; p.r1 = r1v;
        p.g = exp2f(2.0f * q00);
        p.lz = lz; p.uz = uz; p.ly = ly; p.lx = lx;
        const int nx = ux - lx + 1;
        p.nx = nx;
        p.nyx = (uy - ly + 1) * nx;
        p.magic = (unsigned)((0xFFFFFFFFull + (unsigned)nx) / (unsigned)nx); // ceil(2^32/nx)
    }
    g_params[n] = p;
}

__global__ __launch_bounds__(256) void splat_kernel(float* __restrict__ out)
{
    #pragma unroll 1
    for (int i = 0; i < GPC; ++i) {
        const int n = blockIdx.x * GPC + i;
        const PParams p = g_params[n];   // uniform broadcast loads, L2-resident
        if (!p.valid) continue;

        const int nx = p.nx, nyx = p.nyx;
        const int lz = p.lz, uz = p.uz, ly = p.ly, lx = p.lx;
        const unsigned magic = p.magic;

        for (int t = threadIdx.x; t < nyx; t += 256) {
            const unsigned mask = __activemask();

            // division-free t/nx (exact for t < 2^16, nx <= 32)
            const int iy = (int)(((unsigned long long)(unsigned)t * magic) >> 32);
            const int ix = t - iy * nx;
            const int Y = ly + iy;
            const int X = lx + ix;
            const float dy = (float)Y - p.cy;
            const float dx = (float)X - p.cx;

            // e2(dz) = q00*dz^2 + qcl*dz + qeyx  (log2-domain; keep e2 >= E2T)
            const float qcl  = p.a01 * dy + p.a02 * dx;
            const float qeyx = p.b11 * dy * dy + (p.b22 * dx + p.b12 * dy) * dx;

            // per-column valid z-range from quadratic roots (q00 < 0)
            int z0l = 0x7FFFFFFF, z1l = -0x7FFFFFFF;
            const float disc = qcl * qcl - 4.0f * p.q00 * (qeyx - E2T);
            if (disc > 0.0f) {
                const float s = sqrt_approx(disc);
                const float za = (-qcl + s) * p.inv2q;
                const float zb = (-qcl - s) * p.inv2q;
                z0l = max(lz, __float2int_ru(p.cz + fminf(za, zb)));
                z1l = min(uz, __float2int_rd(p.cz + fmaxf(za, zb)));
            }

            // warp-union z loop keeps RED addresses coalesced
            const int z0w = __reduce_min_sync(mask, z0l);
            const int z1w = __reduce_max_sync(mask, z1l);
            if (z0w > z1w) continue;

            // seed recurrence at the warp-uniform z0w; predicate on w >= WTH
            // (w stays >= ~2^-110 over <=19 union steps: no underflow)
            const float dz0 = (float)z0w - p.cz;
            float w = ex2f(fmaf(dz0, fmaf(p.q00, dz0, qcl), qeyx));
            float m = ex2f(fmaf(p.q00, 2.0f * dz0 + 1.0f, qcl));

            float* dst = out + 2u * (unsigned)(z0w * GHW + Y * GW + X);
            for (int Z = z0w; Z <= z1w; ++Z) {
                if (w >= WTH) {
                    const float w0 = w * p.r0;
                    const float w1 = w * p.r1;
                    asm volatile("red.global.add.v2.f32 [%0], {%1, %2};"
                                 :: "l"(dst), "f"(w0), "f"(w1)
                                 : "memory");
                }
                w *= m;
                m *= p.g;
                dst += 2 * GHW;
            }
        }
    }
}

extern "C" void kernel_launch(void* const* d_in, const int* in_sizes, int n_in,
                              void* d_out, int out_size) {
    const float* centers    = (const float*)d_in[0];
    const float* log_scales = (const float*)d_in[1];
    const float* quats      = (const float*)d_in[2];
    const float* rho        = (const float*)d_in[3];
    float* out = (float*)d_out;

    zero_precompute_kernel<<<ZERO_CTAS, 256>>>(centers, log_scales, quats, rho,
                                               (float4*)out);
    splat_kernel<<<SPLAT_CTAS, 256>>>(out);
}